// round 5
// baseline (speedup 1.0000x reference)
#include <cuda_runtime.h>
#include <cstdint>

#define N_NODES 100000
#define N_EDGES 1600000
#define IN_CH   512
#define HID_CH  256
#define OUT_CH  64
#define K_STEPS 10
#define NB_SCAN ((N_NODES + 255) / 256)   // 391

// ---------------- scratch (static __device__, no allocation) ----------------
__device__ int   g_deg[N_NODES];
__device__ int   g_cursor[N_NODES];
__device__ float g_dinv[N_NODES];
__device__ float g_selfw[N_NODES];        // 0.9 * dinv^2
__device__ int   g_rowptr[N_NODES + 1];
__device__ int   g_part[NB_SCAN];
__device__ __align__(16) int2  g_epack[N_EDGES];   // {src, bitcast(0.9*norm)}
__device__ __align__(16) float g_hid [(size_t)N_NODES * HID_CH];
__device__ __align__(16) float g_h0  [(size_t)N_NODES * OUT_CH];
__device__ __align__(16) float g_htmp[(size_t)N_NODES * OUT_CH];

// ---------------- preprocessing ----------------
__global__ void init_deg_cursor()
{
    int i = blockIdx.x * blockDim.x + threadIdx.x;
    if (i < N_NODES) { g_deg[i] = 1; g_cursor[i] = 0; }
}

__global__ void count_deg(const int* __restrict__ ei)
{
    int e = blockIdx.x * blockDim.x + threadIdx.x;
    if (e < N_EDGES) {
        int d = ei[N_EDGES + e];
        if ((unsigned)d < N_NODES) atomicAdd(&g_deg[d], 1);
    }
}

__global__ void compute_dinv()
{
    int i = blockIdx.x * blockDim.x + threadIdx.x;
    if (i < N_NODES) {
        float dv = rsqrtf((float)g_deg[i]);
        g_dinv[i]  = dv;
        g_selfw[i] = 0.9f * dv * dv;
    }
}

__global__ void scan_p1()
{
    int b = blockIdx.x, t = threadIdx.x;
    int i = b * 256 + t;
    int v = (i < N_NODES) ? (g_deg[i] - 1) : 0;
    int lane = t & 31, w = t >> 5;
    int x = v;
    #pragma unroll
    for (int o = 1; o < 32; o <<= 1) {
        int y = __shfl_up_sync(0xffffffffu, x, o);
        if (lane >= o) x += y;
    }
    __shared__ int wsum[8];
    if (lane == 31) wsum[w] = x;
    __syncthreads();
    if (t < 8) {
        int s = wsum[t];
        #pragma unroll
        for (int o = 1; o < 8; o <<= 1) {
            int y = __shfl_up_sync(0xffu, s, o);
            if (t >= o) s += y;
        }
        wsum[t] = s;
    }
    __syncthreads();
    int base = (w > 0) ? wsum[w - 1] : 0;
    if (i < N_NODES) g_rowptr[i] = base + x - v;
    if (t == 255) g_part[b] = wsum[7];
}

__global__ void scan_p2()
{
    __shared__ int s[512];
    int t = threadIdx.x;
    int v = (t < NB_SCAN) ? g_part[t] : 0;
    s[t] = v;
    __syncthreads();
    for (int o = 1; o < 512; o <<= 1) {
        int y = (t >= o) ? s[t - o] : 0;
        __syncthreads();
        s[t] += y;
        __syncthreads();
    }
    if (t < NB_SCAN) g_part[t] = s[t] - v;
    if (t == NB_SCAN - 1) g_rowptr[N_NODES] = s[t];
}

__global__ void scan_p3()
{
    int b = blockIdx.x, t = threadIdx.x;
    int i = b * 256 + t;
    if (i < N_NODES) g_rowptr[i] += g_part[b];
}

__global__ void fill_csr(const int* __restrict__ ei)
{
    int idx = blockIdx.x * blockDim.x + threadIdx.x;
    if (idx < N_EDGES) {
        int s = ei[idx];
        int d = ei[N_EDGES + idx];
        if ((unsigned)s >= N_NODES || (unsigned)d >= N_NODES) return;
        int pos = g_rowptr[d] + atomicAdd(&g_cursor[d], 1);
        int2 p;
        p.x = s;
        p.y = __float_as_int(0.9f * g_dinv[s] * g_dinv[d]);
        g_epack[pos] = p;
    }
}

// ---------------- tf32 tensor-core GEMM ----------------
__device__ __forceinline__ unsigned f2tf32(float f)
{
    unsigned r;
    asm("cvt.rna.tf32.f32 %0, %1;" : "=r"(r) : "f"(f));
    return r;
}

#define MMA_TF32(d, a, b)                                                        \
    asm volatile("mma.sync.aligned.m16n8k8.row.col.f32.tf32.tf32.f32 "           \
                 "{%0,%1,%2,%3},{%4,%5,%6,%7},{%8,%9},{%0,%1,%2,%3};\n"          \
                 : "+f"(d[0]), "+f"(d[1]), "+f"(d[2]), "+f"(d[3])                \
                 : "r"(a[0]), "r"(a[1]), "r"(a[2]), "r"(a[3]),                   \
                   "r"(b[0]), "r"(b[1]))

// BM=128, BK=16, 256 threads, 8 warps as 4(m) x 2(n). Warp tile 32 x BN/2.
// grid: blockIdx.x = N-tile (fast-varying -> A-tile reuse in L2), blockIdx.y = M-tile.
// Double-buffered smem, tf32 pre-converted at store time.
template<int BN, bool RELU>
__global__ __launch_bounds__(256) void gemm_kernel(
    const float* __restrict__ A, const float* __restrict__ B,
    const float* __restrict__ bias, float* __restrict__ C,
    int M, int N, int Kd)
{
    const int BM = 128, BK = 16;
    const int NT = BN / 16;        // n-frags per warp
    const int NCH = BN / 64;       // B staging chunks per thread (1 or 2)
    __shared__ unsigned As[2][BM][BK + 4];
    __shared__ unsigned Bs[2][BK][BN + 8];

    int tid  = threadIdx.x;
    int warp = tid >> 5, lane = tid & 31;
    int wm = warp >> 1;            // 0..3
    int wn = warp & 1;             // 0..1
    int bm0 = blockIdx.y * BM;
    int bn0 = blockIdx.x * BN;

    int arow = tid >> 2, ac4 = tid & 3;

    float acc[2][NT][4];
    #pragma unroll
    for (int i = 0; i < 2; i++)
        #pragma unroll
        for (int j = 0; j < NT; j++)
            #pragma unroll
            for (int l = 0; l < 4; l++) acc[i][j][l] = 0.0f;

    float4 ra[2], rbv[NCH];
    auto load_tile = [&](int k0) {
        #pragma unroll
        for (int i = 0; i < 2; i++) {
            int gr = bm0 + arow + i * 64;
            if (gr < M) ra[i] = *(const float4*)&A[(size_t)gr * Kd + k0 + ac4 * 4];
            else        ra[i] = make_float4(0.f, 0.f, 0.f, 0.f);
        }
        #pragma unroll
        for (int i = 0; i < NCH; i++) {
            int idx = tid + i * 256;
            int brow = idx / (BN / 4), bc4 = idx % (BN / 4);
            rbv[i] = *(const float4*)&B[(size_t)(k0 + brow) * N + bn0 + bc4 * 4];
        }
    };
    auto store_tile = [&](int buf) {
        #pragma unroll
        for (int i = 0; i < 2; i++) {
            unsigned* p = &As[buf][arow + i * 64][ac4 * 4];
            p[0] = f2tf32(ra[i].x); p[1] = f2tf32(ra[i].y);
            p[2] = f2tf32(ra[i].z); p[3] = f2tf32(ra[i].w);
        }
        #pragma unroll
        for (int i = 0; i < NCH; i++) {
            int idx = tid + i * 256;
            int brow = idx / (BN / 4), bc4 = idx % (BN / 4);
            unsigned* q = &Bs[buf][brow][bc4 * 4];
            q[0] = f2tf32(rbv[i].x); q[1] = f2tf32(rbv[i].y);
            q[2] = f2tf32(rbv[i].z); q[3] = f2tf32(rbv[i].w);
        }
    };

    load_tile(0);
    store_tile(0);
    __syncthreads();

    int nIter = Kd / BK;
    for (int it = 0; it < nIter; it++) {
        int cur = it & 1;
        if (it + 1 < nIter) load_tile((it + 1) * BK);

        #pragma unroll
        for (int kc = 0; kc < 2; kc++) {
            unsigned a[2][4], b[NT][2];
            #pragma unroll
            for (int mt = 0; mt < 2; mt++) {
                int r = wm * 32 + mt * 16 + (lane >> 2);
                int c = kc * 8 + (lane & 3);
                a[mt][0] = As[cur][r][c];
                a[mt][1] = As[cur][r + 8][c];
                a[mt][2] = As[cur][r][c + 4];
                a[mt][3] = As[cur][r + 8][c + 4];
            }
            #pragma unroll
            for (int nt = 0; nt < NT; nt++) {
                int col = wn * (BN / 2) + nt * 8 + (lane >> 2);
                int kr  = kc * 8 + (lane & 3);
                b[nt][0] = Bs[cur][kr][col];
                b[nt][1] = Bs[cur][kr + 4][col];
            }
            #pragma unroll
            for (int mt = 0; mt < 2; mt++)
                #pragma unroll
                for (int nt = 0; nt < NT; nt++)
                    MMA_TF32(acc[mt][nt], a[mt], b[nt]);
        }

        if (it + 1 < nIter) {
            store_tile(1 - cur);
            __syncthreads();
        }
    }

    #pragma unroll
    for (int mt = 0; mt < 2; mt++) {
        #pragma unroll
        for (int nt = 0; nt < NT; nt++) {
            int r0 = bm0 + wm * 32 + mt * 16 + (lane >> 2);
            int c0 = bn0 + wn * (BN / 2) + nt * 8 + (lane & 3) * 2;
            float bv0 = bias[c0], bv1 = bias[c0 + 1];
            #pragma unroll
            for (int h = 0; h < 2; h++) {
                int r = r0 + h * 8;
                if (r < M) {
                    float v0 = acc[mt][nt][h * 2 + 0] + bv0;
                    float v1 = acc[mt][nt][h * 2 + 1] + bv1;
                    if (RELU) { v0 = fmaxf(v0, 0.f); v1 = fmaxf(v1, 0.f); }
                    C[(size_t)r * N + c0]     = v0;
                    C[(size_t)r * N + c0 + 1] = v1;
                }
            }
        }
    }
}

// ---------------- propagation (fp32, R3-proven) ----------------
// h_out = sum_e w_e * h_in[src_e] + selfw[v]*h_in[v] + 0.1*h0[v]
// 16 threads per node, each owns one float4 (4 channels) of the 64-ch feature.
__global__ __launch_bounds__(256) void prop_kernel(
    const float* __restrict__ hin, float* __restrict__ hout,
    const float* __restrict__ h0)
{
    int gt = blockIdx.x * blockDim.x + threadIdx.x;
    int v = gt >> 4;
    if (v >= N_NODES) return;
    int lane = gt & 15;

    int e0 = g_rowptr[v];
    int e1 = g_rowptr[v + 1];
    const float4* h4 = (const float4*)hin;

    float4 acc = make_float4(0.f, 0.f, 0.f, 0.f);
    int e = e0;
    for (; e + 2 <= e1; e += 2) {
        int2 p0 = __ldg(&g_epack[e]);
        int2 p1 = __ldg(&g_epack[e + 1]);
        float4 hv0 = h4[(size_t)p0.x * 16 + lane];
        float4 hv1 = h4[(size_t)p1.x * 16 + lane];
        float w0 = __int_as_float(p0.y);
        float w1 = __int_as_float(p1.y);
        acc.x = fmaf(w0, hv0.x, acc.x); acc.y = fmaf(w0, hv0.y, acc.y);
        acc.z = fmaf(w0, hv0.z, acc.z); acc.w = fmaf(w0, hv0.w, acc.w);
        acc.x = fmaf(w1, hv1.x, acc.x); acc.y = fmaf(w1, hv1.y, acc.y);
        acc.z = fmaf(w1, hv1.z, acc.z); acc.w = fmaf(w1, hv1.w, acc.w);
    }
    if (e < e1) {
        int2 p = __ldg(&g_epack[e]);
        float w = __int_as_float(p.y);
        float4 hv = h4[(size_t)p.x * 16 + lane];
        acc.x = fmaf(w, hv.x, acc.x); acc.y = fmaf(w, hv.y, acc.y);
        acc.z = fmaf(w, hv.z, acc.z); acc.w = fmaf(w, hv.w, acc.w);
    }

    float sw = g_selfw[v];
    float4 hs = h4[(size_t)v * 16 + lane];
    float4 z  = ((const float4*)h0)[(size_t)v * 16 + lane];
    float4 r;
    r.x = fmaf(sw, hs.x, acc.x) + 0.1f * z.x;
    r.y = fmaf(sw, hs.y, acc.y) + 0.1f * z.y;
    r.z = fmaf(sw, hs.z, acc.z) + 0.1f * z.z;
    r.w = fmaf(sw, hs.w, acc.w) + 0.1f * z.w;
    ((float4*)hout)[(size_t)v * 16 + lane] = r;
}

// ---------------- launch ----------------
extern "C" void kernel_launch(void* const* d_in, const int* in_sizes, int n_in,
                              void* d_out, int out_size)
{
    const float* x  = (const float*)d_in[0];
    const int*   ei = (const int*)d_in[1];     // int32 [2, E]
    const float* w1 = (const float*)d_in[2];
    const float* b1 = (const float*)d_in[3];
    const float* w2 = (const float*)d_in[4];
    const float* b2 = (const float*)d_in[5];
    float*       out = (float*)d_out;

    float *p_hid, *p_h0, *p_htmp;
    cudaGetSymbolAddress((void**)&p_hid,  g_hid);
    cudaGetSymbolAddress((void**)&p_h0,   g_h0);
    cudaGetSymbolAddress((void**)&p_htmp, g_htmp);

    // launches 1-3: cheap preprocessing
    init_deg_cursor<<<(N_NODES + 255) / 256, 256>>>();
    count_deg<<<(N_EDGES + 255) / 256, 256>>>(ei);
    compute_dinv<<<(N_NODES + 255) / 256, 256>>>();

    // launch 4 (ncu slot): GEMM1 — BN=128, N-tile fast-varying for L2 A-reuse
    dim3 g1(HID_CH / 128, (N_NODES + 127) / 128);
    gemm_kernel<128, true><<<g1, 256>>>(x, w1, b1, p_hid, N_NODES, HID_CH, IN_CH);

    scan_p1<<<NB_SCAN, 256>>>();
    scan_p2<<<1, 512>>>();
    scan_p3<<<NB_SCAN, 256>>>();
    fill_csr<<<(N_EDGES + 255) / 256, 256>>>(ei);

    // GEMM2: h0 = hid @ w2 + b2   (N=64, single N-tile)
    dim3 g2(1, (N_NODES + 127) / 128);
    gemm_kernel<64, false><<<g2, 256>>>(p_hid, w2, b2, p_h0, N_NODES, OUT_CH, HID_CH);

    // APPNP propagation: K=10 steps, ping-pong so the last (odd) step hits d_out
    const float* cur = p_h0;
    int grid = (N_NODES * 16 + 255) / 256;
    for (int s = 0; s < K_STEPS; s++) {
        float* o = (s & 1) ? out : p_htmp;
        prop_kernel<<<grid, 256>>>(cur, o, p_h0);
        cur = o;
    }
}

// round 6
// speedup vs baseline: 1.7011x; 1.7011x over previous
#include <cuda_runtime.h>
#include <cuda_fp16.h>
#include <cstdint>

#define N_NODES 100000
#define N_EDGES 1600000
#define IN_CH   512
#define HID_CH  256
#define OUT_CH  64
#define K_STEPS 10
#define NB_SCAN ((N_NODES + 255) / 256)   // 391

// ---------------- scratch (static __device__, no allocation) ----------------
__device__ int   g_deg[N_NODES];
__device__ int   g_cursor[N_NODES];
__device__ float g_dinv[N_NODES];
__device__ float g_selfw[N_NODES];        // 0.9 * dinv^2
__device__ int   g_rowptr[N_NODES + 1];
__device__ int   g_part[NB_SCAN];
__device__ __align__(16) int2   g_epack[N_EDGES];  // {src, bitcast(0.9*norm)}
__device__ __align__(16) float  g_hid [(size_t)N_NODES * HID_CH];
__device__ __align__(16) float  g_h0  [(size_t)N_NODES * OUT_CH];   // fp32 alpha term
__device__ __align__(16) __half g_h0h [(size_t)N_NODES * OUT_CH];   // fp16 step-0 input
__device__ __align__(16) __half g_ha  [(size_t)N_NODES * OUT_CH];
__device__ __align__(16) __half g_hb  [(size_t)N_NODES * OUT_CH];

// ---------------- preprocessing ----------------
__global__ void init_deg_cursor()
{
    int i = blockIdx.x * blockDim.x + threadIdx.x;
    if (i < N_NODES) { g_deg[i] = 1; g_cursor[i] = 0; }
}

__global__ void count_deg(const int* __restrict__ ei)
{
    int e = blockIdx.x * blockDim.x + threadIdx.x;
    if (e < N_EDGES) {
        int d = ei[N_EDGES + e];
        if ((unsigned)d < N_NODES) atomicAdd(&g_deg[d], 1);
    }
}

__global__ void compute_dinv()
{
    int i = blockIdx.x * blockDim.x + threadIdx.x;
    if (i < N_NODES) {
        float dv = rsqrtf((float)g_deg[i]);
        g_dinv[i]  = dv;
        g_selfw[i] = 0.9f * dv * dv;
    }
}

__global__ void scan_p1()
{
    int b = blockIdx.x, t = threadIdx.x;
    int i = b * 256 + t;
    int v = (i < N_NODES) ? (g_deg[i] - 1) : 0;
    int lane = t & 31, w = t >> 5;
    int x = v;
    #pragma unroll
    for (int o = 1; o < 32; o <<= 1) {
        int y = __shfl_up_sync(0xffffffffu, x, o);
        if (lane >= o) x += y;
    }
    __shared__ int wsum[8];
    if (lane == 31) wsum[w] = x;
    __syncthreads();
    if (t < 8) {
        int s = wsum[t];
        #pragma unroll
        for (int o = 1; o < 8; o <<= 1) {
            int y = __shfl_up_sync(0xffu, s, o);
            if (t >= o) s += y;
        }
        wsum[t] = s;
    }
    __syncthreads();
    int base = (w > 0) ? wsum[w - 1] : 0;
    if (i < N_NODES) g_rowptr[i] = base + x - v;
    if (t == 255) g_part[b] = wsum[7];
}

__global__ void scan_p2()
{
    __shared__ int s[512];
    int t = threadIdx.x;
    int v = (t < NB_SCAN) ? g_part[t] : 0;
    s[t] = v;
    __syncthreads();
    for (int o = 1; o < 512; o <<= 1) {
        int y = (t >= o) ? s[t - o] : 0;
        __syncthreads();
        s[t] += y;
        __syncthreads();
    }
    if (t < NB_SCAN) g_part[t] = s[t] - v;
    if (t == NB_SCAN - 1) g_rowptr[N_NODES] = s[t];
}

__global__ void scan_p3()
{
    int b = blockIdx.x, t = threadIdx.x;
    int i = b * 256 + t;
    if (i < N_NODES) g_rowptr[i] += g_part[b];
}

__global__ void fill_csr(const int* __restrict__ ei)
{
    int idx = blockIdx.x * blockDim.x + threadIdx.x;
    if (idx < N_EDGES) {
        int s = ei[idx];
        int d = ei[N_EDGES + idx];
        if ((unsigned)s >= N_NODES || (unsigned)d >= N_NODES) return;
        int pos = g_rowptr[d] + atomicAdd(&g_cursor[d], 1);
        int2 p;
        p.x = s;
        p.y = __float_as_int(0.9f * g_dinv[s] * g_dinv[d]);
        g_epack[pos] = p;
    }
}

// ---------------- tf32 tensor-core GEMM (unchanged from R5) ----------------
__device__ __forceinline__ unsigned f2tf32(float f)
{
    unsigned r;
    asm("cvt.rna.tf32.f32 %0, %1;" : "=r"(r) : "f"(f));
    return r;
}

#define MMA_TF32(d, a, b)                                                        \
    asm volatile("mma.sync.aligned.m16n8k8.row.col.f32.tf32.tf32.f32 "           \
                 "{%0,%1,%2,%3},{%4,%5,%6,%7},{%8,%9},{%0,%1,%2,%3};\n"          \
                 : "+f"(d[0]), "+f"(d[1]), "+f"(d[2]), "+f"(d[3])                \
                 : "r"(a[0]), "r"(a[1]), "r"(a[2]), "r"(a[3]),                   \
                   "r"(b[0]), "r"(b[1]))

template<int BN, bool RELU, bool DUAL>
__global__ __launch_bounds__(256) void gemm_kernel(
    const float* __restrict__ A, const float* __restrict__ B,
    const float* __restrict__ bias, float* __restrict__ C,
    __half* __restrict__ Ch,
    int M, int N, int Kd)
{
    const int BM = 128, BK = 16;
    const int NT = BN / 16;
    const int NCH = BN / 64;
    __shared__ unsigned As[2][BM][BK + 4];
    __shared__ unsigned Bs[2][BK][BN + 8];

    int tid  = threadIdx.x;
    int warp = tid >> 5, lane = tid & 31;
    int wm = warp >> 1;
    int wn = warp & 1;
    int bm0 = blockIdx.y * BM;
    int bn0 = blockIdx.x * BN;

    int arow = tid >> 2, ac4 = tid & 3;

    float acc[2][NT][4];
    #pragma unroll
    for (int i = 0; i < 2; i++)
        #pragma unroll
        for (int j = 0; j < NT; j++)
            #pragma unroll
            for (int l = 0; l < 4; l++) acc[i][j][l] = 0.0f;

    float4 ra[2], rbv[NCH];
    auto load_tile = [&](int k0) {
        #pragma unroll
        for (int i = 0; i < 2; i++) {
            int gr = bm0 + arow + i * 64;
            if (gr < M) ra[i] = *(const float4*)&A[(size_t)gr * Kd + k0 + ac4 * 4];
            else        ra[i] = make_float4(0.f, 0.f, 0.f, 0.f);
        }
        #pragma unroll
        for (int i = 0; i < NCH; i++) {
            int idx = tid + i * 256;
            int brow = idx / (BN / 4), bc4 = idx % (BN / 4);
            rbv[i] = *(const float4*)&B[(size_t)(k0 + brow) * N + bn0 + bc4 * 4];
        }
    };
    auto store_tile = [&](int buf) {
        #pragma unroll
        for (int i = 0; i < 2; i++) {
            unsigned* p = &As[buf][arow + i * 64][ac4 * 4];
            p[0] = f2tf32(ra[i].x); p[1] = f2tf32(ra[i].y);
            p[2] = f2tf32(ra[i].z); p[3] = f2tf32(ra[i].w);
        }
        #pragma unroll
        for (int i = 0; i < NCH; i++) {
            int idx = tid + i * 256;
            int brow = idx / (BN / 4), bc4 = idx % (BN / 4);
            unsigned* q = &Bs[buf][brow][bc4 * 4];
            q[0] = f2tf32(rbv[i].x); q[1] = f2tf32(rbv[i].y);
            q[2] = f2tf32(rbv[i].z); q[3] = f2tf32(rbv[i].w);
        }
    };

    load_tile(0);
    store_tile(0);
    __syncthreads();

    int nIter = Kd / BK;
    for (int it = 0; it < nIter; it++) {
        int cur = it & 1;
        if (it + 1 < nIter) load_tile((it + 1) * BK);

        #pragma unroll
        for (int kc = 0; kc < 2; kc++) {
            unsigned a[2][4], b[NT][2];
            #pragma unroll
            for (int mt = 0; mt < 2; mt++) {
                int r = wm * 32 + mt * 16 + (lane >> 2);
                int c = kc * 8 + (lane & 3);
                a[mt][0] = As[cur][r][c];
                a[mt][1] = As[cur][r + 8][c];
                a[mt][2] = As[cur][r][c + 4];
                a[mt][3] = As[cur][r + 8][c + 4];
            }
            #pragma unroll
            for (int nt = 0; nt < NT; nt++) {
                int col = wn * (BN / 2) + nt * 8 + (lane >> 2);
                int kr  = kc * 8 + (lane & 3);
                b[nt][0] = Bs[cur][kr][col];
                b[nt][1] = Bs[cur][kr + 4][col];
            }
            #pragma unroll
            for (int mt = 0; mt < 2; mt++)
                #pragma unroll
                for (int nt = 0; nt < NT; nt++)
                    MMA_TF32(acc[mt][nt], a[mt], b[nt]);
        }

        if (it + 1 < nIter) {
            store_tile(1 - cur);
            __syncthreads();
        }
    }

    #pragma unroll
    for (int mt = 0; mt < 2; mt++) {
        #pragma unroll
        for (int nt = 0; nt < NT; nt++) {
            int r0 = bm0 + wm * 32 + mt * 16 + (lane >> 2);
            int c0 = bn0 + wn * (BN / 2) + nt * 8 + (lane & 3) * 2;
            float bv0 = bias[c0], bv1 = bias[c0 + 1];
            #pragma unroll
            for (int h = 0; h < 2; h++) {
                int r = r0 + h * 8;
                if (r < M) {
                    float v0 = acc[mt][nt][h * 2 + 0] + bv0;
                    float v1 = acc[mt][nt][h * 2 + 1] + bv1;
                    if (RELU) { v0 = fmaxf(v0, 0.f); v1 = fmaxf(v1, 0.f); }
                    C[(size_t)r * N + c0]     = v0;
                    C[(size_t)r * N + c0 + 1] = v1;
                    if (DUAL) {
                        *(__half2*)&Ch[(size_t)r * N + c0] = __floats2half2_rn(v0, v1);
                    }
                }
            }
        }
    }
}

// ---------------- propagation (fp16 storage, fp32 accumulation) ----------------
// h_out = sum_e w_e*h_in[src_e] + selfw[v]*h_in[v] + 0.1*h0[v]
// 16 threads per node; each lane owns 4 channels = 8B of the 128B fp16 row.
// Edge data consumed as int4 (two packed edges) when 16B-aligned.
template<bool OUT_HALF>
__global__ __launch_bounds__(256) void prop_kernel(
    const __half* __restrict__ hin, void* __restrict__ hout,
    const float* __restrict__ h0)
{
    int gt = blockIdx.x * blockDim.x + threadIdx.x;
    int v = gt >> 4;
    if (v >= N_NODES) return;
    int lane = gt & 15;

    int e0 = g_rowptr[v];
    int e1 = g_rowptr[v + 1];
    const uint2* h2 = (const uint2*)hin;

    float4 acc = make_float4(0.f, 0.f, 0.f, 0.f);
    auto accum = [&](float w, uint2 hv) {
        float2 lo = __half22float2(*(const __half2*)&hv.x);
        float2 hi = __half22float2(*(const __half2*)&hv.y);
        acc.x = fmaf(w, lo.x, acc.x); acc.y = fmaf(w, lo.y, acc.y);
        acc.z = fmaf(w, hi.x, acc.z); acc.w = fmaf(w, hi.y, acc.w);
    };

    int e = e0;
    if ((e & 1) && e < e1) {              // align to int4 boundary
        int2 p = __ldg(&g_epack[e]);
        accum(__int_as_float(p.y), h2[(size_t)p.x * 16 + lane]);
        e++;
    }
    for (; e + 2 <= e1; e += 2) {         // two edges per 16B load
        int4 p = __ldg((const int4*)&g_epack[e]);
        uint2 hv0 = h2[(size_t)p.x * 16 + lane];
        uint2 hv1 = h2[(size_t)p.z * 16 + lane];
        accum(__int_as_float(p.y), hv0);
        accum(__int_as_float(p.w), hv1);
    }
    if (e < e1) {
        int2 p = __ldg(&g_epack[e]);
        accum(__int_as_float(p.y), h2[(size_t)p.x * 16 + lane]);
    }

    // self-loop term
    accum(g_selfw[v], h2[(size_t)v * 16 + lane]);

    // alpha * h0 (fp32, exact)
    float4 z = ((const float4*)h0)[(size_t)v * 16 + lane];
    float4 r;
    r.x = acc.x + 0.1f * z.x;
    r.y = acc.y + 0.1f * z.y;
    r.z = acc.z + 0.1f * z.z;
    r.w = acc.w + 0.1f * z.w;

    if (OUT_HALF) {
        uint2 o;
        *(__half2*)&o.x = __floats2half2_rn(r.x, r.y);
        *(__half2*)&o.y = __floats2half2_rn(r.z, r.w);
        ((uint2*)hout)[(size_t)v * 16 + lane] = o;
    } else {
        ((float4*)hout)[(size_t)v * 16 + lane] = r;
    }
}

// ---------------- launch ----------------
extern "C" void kernel_launch(void* const* d_in, const int* in_sizes, int n_in,
                              void* d_out, int out_size)
{
    const float* x  = (const float*)d_in[0];
    const int*   ei = (const int*)d_in[1];     // int32 [2, E]
    const float* w1 = (const float*)d_in[2];
    const float* b1 = (const float*)d_in[3];
    const float* w2 = (const float*)d_in[4];
    const float* b2 = (const float*)d_in[5];
    float*       out = (float*)d_out;

    float *p_hid, *p_h0;
    __half *p_h0h, *p_ha, *p_hb;
    cudaGetSymbolAddress((void**)&p_hid, g_hid);
    cudaGetSymbolAddress((void**)&p_h0,  g_h0);
    cudaGetSymbolAddress((void**)&p_h0h, g_h0h);
    cudaGetSymbolAddress((void**)&p_ha,  g_ha);
    cudaGetSymbolAddress((void**)&p_hb,  g_hb);

    // launches 0-2: cheap preprocessing
    init_deg_cursor<<<(N_NODES + 255) / 256, 256>>>();
    count_deg<<<(N_EDGES + 255) / 256, 256>>>(ei);
    compute_dinv<<<(N_NODES + 255) / 256, 256>>>();

    // launch index 3 (ncu slot): GEMM1 — BN=128, N-tile fast-varying for L2 A-reuse
    dim3 g1(HID_CH / 128, (N_NODES + 127) / 128);
    gemm_kernel<128, true, false><<<g1, 256>>>(x, w1, b1, p_hid, nullptr,
                                               N_NODES, HID_CH, IN_CH);

    scan_p1<<<NB_SCAN, 256>>>();
    scan_p2<<<1, 512>>>();
    scan_p3<<<NB_SCAN, 256>>>();
    fill_csr<<<(N_EDGES + 255) / 256, 256>>>(ei);

    // GEMM2: fp32 h0 (alpha term) + fp16 h0 (step-0 propagation input)
    dim3 g2(1, (N_NODES + 127) / 128);
    gemm_kernel<64, false, true><<<g2, 256>>>(p_hid, w2, b2, p_h0, p_h0h,
                                              N_NODES, OUT_CH, HID_CH);

    // APPNP: steps 0..8 fp16 ping-pong, step 9 writes fp32 to d_out
    int grid = (N_NODES * 16 + 255) / 256;
    const __half* cur = p_h0h;
    for (int s = 0; s < K_STEPS - 1; s++) {
        __half* o = (s & 1) ? p_hb : p_ha;
        prop_kernel<true><<<grid, 256>>>(cur, o, p_h0);
        cur = o;
    }
    prop_kernel<false><<<grid, 256>>>(cur, out, p_h0);
}

// round 8
// speedup vs baseline: 1.7758x; 1.0440x over previous
#include <cuda_runtime.h>
#include <cuda_fp16.h>
#include <cstdint>

#define N_NODES 100000
#define N_EDGES 1600000
#define IN_CH   512
#define HID_CH  256
#define OUT_CH  64
#define K_STEPS 10
#define NB_SCAN ((N_NODES + 255) / 256)   // 391
#define W1_ELEMS (IN_CH * HID_CH)          // 131072
#define W2_ELEMS (HID_CH * OUT_CH)         // 16384

// ---------------- scratch (static __device__, no allocation) ----------------
__device__ int   g_deg[N_NODES];
__device__ int   g_cursor[N_NODES];
__device__ float g_dinv[N_NODES];
__device__ float g_selfw[N_NODES];        // 0.9 * dinv^2
__device__ int   g_rowptr[N_NODES + 1];
__device__ int   g_part[NB_SCAN];
__device__ __align__(16) int2   g_epack[N_EDGES];  // {src, bitcast(0.9*norm)}
__device__ __align__(16) float  g_w1t[W1_ELEMS];   // tf32-rounded w1
__device__ __align__(16) float  g_w2t[W2_ELEMS];   // tf32-rounded w2
__device__ __align__(16) float  g_hid [(size_t)N_NODES * HID_CH];
__device__ __align__(16) float  g_h0  [(size_t)N_NODES * OUT_CH];   // fp32 alpha term
__device__ __align__(16) __half g_h0h [(size_t)N_NODES * OUT_CH];   // fp16 step-0 input
__device__ __align__(16) __half g_ha  [(size_t)N_NODES * OUT_CH];
__device__ __align__(16) __half g_hb  [(size_t)N_NODES * OUT_CH];

__device__ __forceinline__ unsigned f2tf32(float f)
{
    unsigned r;
    asm("cvt.rna.tf32.f32 %0, %1;" : "=r"(r) : "f"(f));
    return r;
}

// ---------------- preprocessing ----------------
// Fused: degree/cursor init + tf32 pre-rounding of w1 and w2 (keeps GEMM1 at
// launch index 3, the slot ncu empirically captures).
__global__ void init_and_round(const float* __restrict__ w1,
                               const float* __restrict__ w2)
{
    int i = blockIdx.x * blockDim.x + threadIdx.x;
    if (i < N_NODES) { g_deg[i] = 1; g_cursor[i] = 0; }
    if (i < W1_ELEMS) g_w1t[i] = __uint_as_float(f2tf32(w1[i]));
    if (i < W2_ELEMS) g_w2t[i] = __uint_as_float(f2tf32(w2[i]));
}

__global__ void count_deg(const int* __restrict__ ei)
{
    int e = blockIdx.x * blockDim.x + threadIdx.x;
    if (e < N_EDGES) {
        int d = ei[N_EDGES + e];
        if ((unsigned)d < N_NODES) atomicAdd(&g_deg[d], 1);
    }
}

__global__ void compute_dinv()
{
    int i = blockIdx.x * blockDim.x + threadIdx.x;
    if (i < N_NODES) {
        float dv = rsqrtf((float)g_deg[i]);
        g_dinv[i]  = dv;
        g_selfw[i] = 0.9f * dv * dv;
    }
}

__global__ void scan_p1()
{
    int b = blockIdx.x, t = threadIdx.x;
    int i = b * 256 + t;
    int v = (i < N_NODES) ? (g_deg[i] - 1) : 0;
    int lane = t & 31, w = t >> 5;
    int x = v;
    #pragma unroll
    for (int o = 1; o < 32; o <<= 1) {
        int y = __shfl_up_sync(0xffffffffu, x, o);
        if (lane >= o) x += y;
    }
    __shared__ int wsum[8];
    if (lane == 31) wsum[w] = x;
    __syncthreads();
    if (t < 8) {
        int s = wsum[t];
        #pragma unroll
        for (int o = 1; o < 8; o <<= 1) {
            int y = __shfl_up_sync(0xffu, s, o);
            if (t >= o) s += y;
        }
        wsum[t] = s;
    }
    __syncthreads();
    int base = (w > 0) ? wsum[w - 1] : 0;
    if (i < N_NODES) g_rowptr[i] = base + x - v;
    if (t == 255) g_part[b] = wsum[7];
}

__global__ void scan_p2()
{
    __shared__ int s[512];
    int t = threadIdx.x;
    int v = (t < NB_SCAN) ? g_part[t] : 0;
    s[t] = v;
    __syncthreads();
    for (int o = 1; o < 512; o <<= 1) {
        int y = (t >= o) ? s[t - o] : 0;
        __syncthreads();
        s[t] += y;
        __syncthreads();
    }
    if (t < NB_SCAN) g_part[t] = s[t] - v;
    if (t == NB_SCAN - 1) g_rowptr[N_NODES] = s[t];
}

__global__ void scan_p3()
{
    int b = blockIdx.x, t = threadIdx.x;
    int i = b * 256 + t;
    if (i < N_NODES) g_rowptr[i] += g_part[b];
}

__global__ void fill_csr(const int* __restrict__ ei)
{
    int idx = blockIdx.x * blockDim.x + threadIdx.x;
    if (idx < N_EDGES) {
        int s = ei[idx];
        int d = ei[N_EDGES + idx];
        if ((unsigned)s >= N_NODES || (unsigned)d >= N_NODES) return;
        int pos = g_rowptr[d] + atomicAdd(&g_cursor[d], 1);
        int2 p;
        p.x = s;
        p.y = __float_as_int(0.9f * g_dinv[s] * g_dinv[d]);
        g_epack[pos] = p;
    }
}

// ---------------- tf32 tensor-core GEMM with cp.async pipeline ----------------
__device__ __forceinline__ void cp_async16(void* smem_dst, const void* gmem_src, bool valid)
{
    unsigned s = (unsigned)__cvta_generic_to_shared(smem_dst);
    int sz = valid ? 16 : 0;
    asm volatile("cp.async.cg.shared.global [%0], [%1], 16, %2;\n"
                 :: "r"(s), "l"(gmem_src), "r"(sz));
}
#define CP_COMMIT() asm volatile("cp.async.commit_group;\n" ::: "memory")
#define CP_WAIT(n)  asm volatile("cp.async.wait_group %0;\n" :: "n"(n) : "memory")

#define MMA_TF32(d, a, b)                                                        \
    asm volatile("mma.sync.aligned.m16n8k8.row.col.f32.tf32.tf32.f32 "           \
                 "{%0,%1,%2,%3},{%4,%5,%6,%7},{%8,%9},{%0,%1,%2,%3};\n"          \
                 : "+f"(d[0]), "+f"(d[1]), "+f"(d[2]), "+f"(d[3])                \
                 : "r"(a[0]), "r"(a[1]), "r"(a[2]), "r"(a[3]),                   \
                   "r"(b[0]), "r"(b[1]))

// BM=128, BK=16, 256 threads, 8 warps as 4(m) x 2(n). Warp tile 32 x BN/2.
// 4-stage cp.async pipeline. A fragments rounded to tf32 with cvt.rna at
// fragment load; B comes pre-rounded (g_w1t/g_w2t) so raw bits are exact.
template<int BN, bool RELU, bool DUAL>
__global__ __launch_bounds__(256) void gemm_kernel(
    const float* __restrict__ A, const float* __restrict__ B,
    const float* __restrict__ bias, float* __restrict__ C,
    __half* __restrict__ Ch,
    int M, int N, int Kd)
{
    const int BM = 128, BK = 16, STAGES = 4;
    const int NT = BN / 16;        // n-frags per warp
    const int NCH = BN / 64;       // B cp.async chunks per thread
    __shared__ float As[STAGES][BM][BK + 4];
    __shared__ float Bs[STAGES][BK][BN + 8];

    int tid  = threadIdx.x;
    int warp = tid >> 5, lane = tid & 31;
    int wm = warp >> 1;
    int wn = warp & 1;
    int bm0 = blockIdx.y * BM;
    int bn0 = blockIdx.x * BN;

    int arow = tid >> 2, ac4 = tid & 3;

    float acc[2][NT][4];
    #pragma unroll
    for (int i = 0; i < 2; i++)
        #pragma unroll
        for (int j = 0; j < NT; j++)
            #pragma unroll
            for (int l = 0; l < 4; l++) acc[i][j][l] = 0.0f;

    auto load_stage = [&](int buf, int k0) {
        #pragma unroll
        for (int i = 0; i < 2; i++) {
            int gr = bm0 + arow + i * 64;
            int cl = (gr < M) ? gr : (M - 1);
            cp_async16(&As[buf][arow + i * 64][ac4 * 4],
                       &A[(size_t)cl * Kd + k0 + ac4 * 4], gr < M);
        }
        #pragma unroll
        for (int i = 0; i < NCH; i++) {
            int idx = tid + i * 256;
            int brow = idx / (BN / 4), bc4 = idx % (BN / 4);
            cp_async16(&Bs[buf][brow][bc4 * 4],
                       &B[(size_t)(k0 + brow) * N + bn0 + bc4 * 4], true);
        }
    };

    int nIter = Kd / BK;
    #pragma unroll
    for (int s = 0; s < STAGES - 1; s++) {
        if (s < nIter) load_stage(s, s * BK);
        CP_COMMIT();
    }

    for (int it = 0; it < nIter; it++) {
        CP_WAIT(STAGES - 2);
        __syncthreads();

        int pf = it + STAGES - 1;
        if (pf < nIter) load_stage(pf % STAGES, pf * BK);
        CP_COMMIT();

        int cur = it % STAGES;
        #pragma unroll
        for (int kc = 0; kc < 2; kc++) {
            unsigned a[2][4], b[NT][2];
            #pragma unroll
            for (int mt = 0; mt < 2; mt++) {
                int r = wm * 32 + mt * 16 + (lane >> 2);
                int c = kc * 8 + (lane & 3);
                a[mt][0] = f2tf32(As[cur][r][c]);
                a[mt][1] = f2tf32(As[cur][r + 8][c]);
                a[mt][2] = f2tf32(As[cur][r][c + 4]);
                a[mt][3] = f2tf32(As[cur][r + 8][c + 4]);
            }
            #pragma unroll
            for (int nt = 0; nt < NT; nt++) {
                int col = wn * (BN / 2) + nt * 8 + (lane >> 2);
                int kr  = kc * 8 + (lane & 3);
                b[nt][0] = __float_as_uint(Bs[cur][kr][col]);
                b[nt][1] = __float_as_uint(Bs[cur][kr + 4][col]);
            }
            #pragma unroll
            for (int mt = 0; mt < 2; mt++)
                #pragma unroll
                for (int nt = 0; nt < NT; nt++)
                    MMA_TF32(acc[mt][nt], a[mt], b[nt]);
        }
    }

    #pragma unroll
    for (int mt = 0; mt < 2; mt++) {
        #pragma unroll
        for (int nt = 0; nt < NT; nt++) {
            int r0 = bm0 + wm * 32 + mt * 16 + (lane >> 2);
            int c0 = bn0 + wn * (BN / 2) + nt * 8 + (lane & 3) * 2;
            float bv0 = bias[c0], bv1 = bias[c0 + 1];
            #pragma unroll
            for (int h = 0; h < 2; h++) {
                int r = r0 + h * 8;
                if (r < M) {
                    float v0 = acc[mt][nt][h * 2 + 0] + bv0;
                    float v1 = acc[mt][nt][h * 2 + 1] + bv1;
                    if (RELU) { v0 = fmaxf(v0, 0.f); v1 = fmaxf(v1, 0.f); }
                    C[(size_t)r * N + c0]     = v0;
                    C[(size_t)r * N + c0 + 1] = v1;
                    if (DUAL) {
                        *(__half2*)&Ch[(size_t)r * N + c0] = __floats2half2_rn(v0, v1);
                    }
                }
            }
        }
    }
}

// ---------------- propagation (fp16 storage, fp32 accumulation) ----------------
template<bool OUT_HALF>
__global__ __launch_bounds__(256) void prop_kernel(
    const __half* __restrict__ hin, void* __restrict__ hout,
    const float* __restrict__ h0)
{
    int gt = blockIdx.x * blockDim.x + threadIdx.x;
    int v = gt >> 4;
    if (v >= N_NODES) return;
    int lane = gt & 15;

    int e0 = g_rowptr[v];
    int e1 = g_rowptr[v + 1];
    const uint2* h2 = (const uint2*)hin;

    float4 acc = make_float4(0.f, 0.f, 0.f, 0.f);
    auto accum = [&](float w, uint2 hv) {
        float2 lo = __half22float2(*(const __half2*)&hv.x);
        float2 hi = __half22float2(*(const __half2*)&hv.y);
        acc.x = fmaf(w, lo.x, acc.x); acc.y = fmaf(w, lo.y, acc.y);
        acc.z = fmaf(w, hi.x, acc.z); acc.w = fmaf(w, hi.y, acc.w);
    };

    int e = e0;
    if ((e & 1) && e < e1) {
        int2 p = __ldg(&g_epack[e]);
        accum(__int_as_float(p.y), h2[(size_t)p.x * 16 + lane]);
        e++;
    }
    for (; e + 2 <= e1; e += 2) {
        int4 p = __ldg((const int4*)&g_epack[e]);
        uint2 hv0 = h2[(size_t)p.x * 16 + lane];
        uint2 hv1 = h2[(size_t)p.z * 16 + lane];
        accum(__int_as_float(p.y), hv0);
        accum(__int_as_float(p.w), hv1);
    }
    if (e < e1) {
        int2 p = __ldg(&g_epack[e]);
        accum(__int_as_float(p.y), h2[(size_t)p.x * 16 + lane]);
    }

    accum(g_selfw[v], h2[(size_t)v * 16 + lane]);

    float4 z = ((const float4*)h0)[(size_t)v * 16 + lane];
    float4 r;
    r.x = acc.x + 0.1f * z.x;
    r.y = acc.y + 0.1f * z.y;
    r.z = acc.z + 0.1f * z.z;
    r.w = acc.w + 0.1f * z.w;

    if (OUT_HALF) {
        uint2 o;
        *(__half2*)&o.x = __floats2half2_rn(r.x, r.y);
        *(__half2*)&o.y = __floats2half2_rn(r.z, r.w);
        ((uint2*)hout)[(size_t)v * 16 + lane] = o;
    } else {
        ((float4*)hout)[(size_t)v * 16 + lane] = r;
    }
}

// ---------------- launch ----------------
extern "C" void kernel_launch(void* const* d_in, const int* in_sizes, int n_in,
                              void* d_out, int out_size)
{
    const float* x  = (const float*)d_in[0];
    const int*   ei = (const int*)d_in[1];     // int32 [2, E]
    const float* w1 = (const float*)d_in[2];
    const float* b1 = (const float*)d_in[3];
    const float* w2 = (const float*)d_in[4];
    const float* b2 = (const float*)d_in[5];
    float*       out = (float*)d_out;

    float *p_hid, *p_h0, *p_w1t, *p_w2t;
    __half *p_h0h, *p_ha, *p_hb;
    cudaGetSymbolAddress((void**)&p_hid, g_hid);
    cudaGetSymbolAddress((void**)&p_h0,  g_h0);
    cudaGetSymbolAddress((void**)&p_w1t, g_w1t);
    cudaGetSymbolAddress((void**)&p_w2t, g_w2t);
    cudaGetSymbolAddress((void**)&p_h0h, g_h0h);
    cudaGetSymbolAddress((void**)&p_ha,  g_ha);
    cudaGetSymbolAddress((void**)&p_hb,  g_hb);

    // launches 0-2: preprocessing (+ tf32 weight pre-rounding fused into 0)
    int init_n = (W1_ELEMS > N_NODES ? W1_ELEMS : N_NODES);
    init_and_round<<<(init_n + 255) / 256, 256>>>(w1, w2);
    count_deg<<<(N_EDGES + 255) / 256, 256>>>(ei);
    compute_dinv<<<(N_NODES + 255) / 256, 256>>>();

    // launch index 3 (ncu slot): GEMM1
    dim3 g1(HID_CH / 128, (N_NODES + 127) / 128);
    gemm_kernel<128, true, false><<<g1, 256>>>(x, p_w1t, b1, p_hid, nullptr,
                                               N_NODES, HID_CH, IN_CH);

    scan_p1<<<NB_SCAN, 256>>>();
    scan_p2<<<1, 512>>>();
    scan_p3<<<NB_SCAN, 256>>>();
    fill_csr<<<(N_EDGES + 255) / 256, 256>>>(ei);

    // GEMM2: fp32 h0 (alpha term) + fp16 h0 (step-0 propagation input)
    dim3 g2(1, (N_NODES + 127) / 128);
    gemm_kernel<64, false, true><<<g2, 256>>>(p_hid, p_w2t, b2, p_h0, p_h0h,
                                              N_NODES, OUT_CH, HID_CH);

    // APPNP: steps 0..8 fp16 ping-pong, step 9 writes fp32 to d_out
    int grid = (N_NODES * 16 + 255) / 256;
    const __half* cur = p_h0h;
    for (int s = 0; s < K_STEPS - 1; s++) {
        __half* o = (s & 1) ? p_hb : p_ha;
        prop_kernel<true><<<grid, 256>>>(cur, o, p_h0);
        cur = o;
    }
    prop_kernel<false><<<grid, 256>>>(cur, out, p_h0);
}